// round 4
// baseline (speedup 1.0000x reference)
#include <cuda_runtime.h>
#include <math.h>

// ZINBDecoder, 8 lanes per edge, 4 edges per warp, persistent grid-stride,
// weights register-resident (amortized over ~200 edges/warp), packed f32x2.
//   h = ufeats[src] * ifeats[dst]  (d=128)
//   mu_  = sigmoid(h.Wm + bm); d_ = h.Wd + bd; pi = sigmoid(h.Wp + bp)
//   disp = clip(softplus(gef*d_), 1e-4, 1e4)
//   mu   = szf * clip(exp(gef*mu_) - 1, 1e-5, 1e6)
// out = [mu | disp | pi], fp32.

#define DV 32   // 16-byte vectors per 128-float row

__device__ __forceinline__ unsigned long long fmul2(unsigned long long a,
                                                    unsigned long long b) {
    unsigned long long d;
    asm("mul.rn.f32x2 %0, %1, %2;" : "=l"(d) : "l"(a), "l"(b));
    return d;
}

__device__ __forceinline__ unsigned long long ffma2(unsigned long long a,
                                                    unsigned long long b,
                                                    unsigned long long c) {
    unsigned long long d;
    asm("fma.rn.f32x2 %0, %1, %2, %3;" : "=l"(d) : "l"(a), "l"(b), "l"(c));
    return d;
}

__device__ __forceinline__ float unpack_sum(unsigned long long p) {
    unsigned int lo, hi;
    asm("mov.b64 {%0, %1}, %2;" : "=r"(lo), "=r"(hi) : "l"(p));
    return __uint_as_float(lo) + __uint_as_float(hi);
}

__device__ __forceinline__ float fast_sigmoid(float x) {
    return __fdividef(1.0f, 1.0f + __expf(-x));
}

__global__ void __launch_bounds__(256)
zinb_kernel(const float* __restrict__ ufeats,
            const float* __restrict__ ifeats,
            const float* __restrict__ ge_factor,
            const float* __restrict__ sz_factor,
            const float* __restrict__ W_mean,
            const float* __restrict__ b_mean,
            const float* __restrict__ W_disp,
            const float* __restrict__ b_disp,
            const float* __restrict__ W_pi,
            const float* __restrict__ b_pi,
            const int*   __restrict__ src_idx,
            const int*   __restrict__ dst_idx,
            float* __restrict__ out,
            int E)
{
    const int tid  = threadIdx.x;
    const int lane = tid & 31;
    const int sub  = lane & 7;        // lane within 8-lane edge group
    const int grp  = lane >> 3;       // edge slot within warp (0..3)

    // Uniform biases, hoisted (loaded once per thread).
    const float bm = b_mean[0];
    const float bd = b_disp[0];
    const float bp = b_pi[0];

    // Per-thread weight slices in registers for the whole persistent loop:
    // k = 0..3, covering elements 2*(k*8+sub) .. 2*(k*8+sub)+3 of each W.
    const ulonglong2* __restrict__ wm2 = reinterpret_cast<const ulonglong2*>(W_mean);
    const ulonglong2* __restrict__ wd2 = reinterpret_cast<const ulonglong2*>(W_disp);
    const ulonglong2* __restrict__ wp2 = reinterpret_cast<const ulonglong2*>(W_pi);
    ulonglong2 wm[4], wd[4], wp[4];
#pragma unroll
    for (int k = 0; k < 4; ++k) {
        wm[k] = wm2[k * 8 + sub];
        wd[k] = wd2[k * 8 + sub];
        wp[k] = wp2[k * 8 + sub];
    }

    const ulonglong2* __restrict__ u2 = reinterpret_cast<const ulonglong2*>(ufeats);
    const ulonglong2* __restrict__ v2 = reinterpret_cast<const ulonglong2*>(ifeats);

    const int       gwarp       = (blockIdx.x * blockDim.x + tid) >> 5;
    const int       total_warps = (gridDim.x * blockDim.x) >> 5;
    const long long stride4     = (long long)total_warps * 4;

    for (long long eb = (long long)gwarp * 4; eb < E; eb += stride4) {
        const long long e_ll  = eb + grp;
        const bool      valid = (e_ll < (long long)E);
        const int       e     = valid ? (int)e_ll : (E - 1);  // clamp: safe loads

        const int s = src_idx[e];
        const int g = dst_idx[e];

        const ulonglong2* __restrict__ up = u2 + (size_t)s * DV + sub;
        const ulonglong2* __restrict__ vp = v2 + (size_t)g * DV + sub;

        unsigned long long am = 0, ad = 0, ap = 0;   // f32x2 accumulators

#pragma unroll
        for (int k = 0; k < 4; ++k) {
            const ulonglong2 u = up[k * 8];
            const ulonglong2 v = vp[k * 8];

            const unsigned long long h01 = fmul2(u.x, v.x);
            const unsigned long long h23 = fmul2(u.y, v.y);

            am = ffma2(h01, wm[k].x, am);
            am = ffma2(h23, wm[k].y, am);
            ad = ffma2(h01, wd[k].x, ad);
            ad = ffma2(h23, wd[k].y, ad);
            ap = ffma2(h01, wp[k].x, ap);
            ap = ffma2(h23, wp[k].y, ap);
        }

        float sm = unpack_sum(am);
        float sd = unpack_sum(ad);
        float sp = unpack_sum(ap);

        // Reduce within each 8-lane group (xor 1,2,4 stay inside the group).
#pragma unroll
        for (int off = 1; off <= 4; off <<= 1) {
            sm += __shfl_xor_sync(0xFFFFFFFFu, sm, off);
            sd += __shfl_xor_sync(0xFFFFFFFFu, sd, off);
            sp += __shfl_xor_sync(0xFFFFFFFFu, sp, off);
        }

        // 4 leader lanes (one per edge) apply activations in parallel.
        if (sub == 0 && valid) {
            const float gef = ge_factor[g];
            const float szf = sz_factor[s];

            const float mu_sig = fast_sigmoid(sm + bm);
            const float pi_v   = fast_sigmoid(sp + bp);

            // stable softplus: max(x,0) + log(1 + exp(-|x|))
            const float x = gef * (sd + bd);
            float disp = fmaxf(x, 0.0f) + __logf(1.0f + __expf(-fabsf(x)));
            disp = fminf(fmaxf(disp, 1e-4f), 1e4f);

            float mu = __expf(gef * mu_sig) - 1.0f;   // arg in [0,1]
            mu = fminf(fmaxf(mu, 1e-5f), 1e6f);
            mu *= szf;

            out[e]         = mu;
            out[E + e]     = disp;
            out[2 * E + e] = pi_v;
        }
    }
}

extern "C" void kernel_launch(void* const* d_in, const int* in_sizes, int n_in,
                              void* d_out, int out_size)
{
    const float* ufeats    = (const float*)d_in[0];
    const float* ifeats    = (const float*)d_in[1];
    const float* ge_factor = (const float*)d_in[2];
    const float* sz_factor = (const float*)d_in[3];
    const float* W_mean    = (const float*)d_in[4];
    const float* b_mean    = (const float*)d_in[5];
    const float* W_disp    = (const float*)d_in[6];
    const float* b_disp    = (const float*)d_in[7];
    const float* W_pi      = (const float*)d_in[8];
    const float* b_pi      = (const float*)d_in[9];
    const int*   src_idx   = (const int*)d_in[10];
    const int*   dst_idx   = (const int*)d_in[11];
    float* out = (float*)d_out;
    (void)n_in; (void)out_size;

    const int E = in_sizes[10];

    // Persistent-ish grid: 1184 blocks x 8 warps, grid-stride (~211 edges/warp).
    const int threads = 256;
    int blocks = 148 * 8;
    long long max_useful = ((long long)E + 31) / 32;   // 32 edges per block-pass
    if ((long long)blocks > max_useful) blocks = (int)max_useful;

    zinb_kernel<<<blocks, threads>>>(
        ufeats, ifeats, ge_factor, sz_factor,
        W_mean, b_mean, W_disp, b_disp, W_pi, b_pi,
        src_idx, dst_idx, out, E);
}

// round 5
// speedup vs baseline: 1.2782x; 1.2782x over previous
#include <cuda_runtime.h>
#include <math.h>

// ZINBDecoder, converged-load layout:
//   - whole warp cooperates on one edge's rows (LDG.32, 1 line/instr)
//   - 4 edges per iteration, ITERS iterations per warp (32 edges/warp)
//   - weights register-resident: 12 scalar regs (W[lane+32k])
//   - reduce-scatter: 12 partials (4 edges x 3 sums) -> per-octet sums
// out = [mu | disp | pi], fp32.

#define ITERS 8   // 4 edges/iter -> 32 edges per warp

__device__ __forceinline__ float fast_sigmoid(float x) {
    return __fdividef(1.0f, 1.0f + __expf(-x));
}

__global__ void __launch_bounds__(256, 4)
zinb_kernel(const float* __restrict__ ufeats,
            const float* __restrict__ ifeats,
            const float* __restrict__ ge_factor,
            const float* __restrict__ sz_factor,
            const float* __restrict__ W_mean,
            const float* __restrict__ b_mean,
            const float* __restrict__ W_disp,
            const float* __restrict__ b_disp,
            const float* __restrict__ W_pi,
            const float* __restrict__ b_pi,
            const int*   __restrict__ src_idx,
            const int*   __restrict__ dst_idx,
            float* __restrict__ out,
            int E)
{
    const int tid  = threadIdx.x;
    const int lane = tid & 31;

    const float bm = b_mean[0];
    const float bd = b_disp[0];
    const float bp = b_pi[0];

    // Weight slices in registers: element (lane + 32k), k = 0..3.
    float wm[4], wd[4], wp[4];
#pragma unroll
    for (int k = 0; k < 4; ++k) {
        wm[k] = W_mean[lane + 32 * k];
        wd[k] = W_disp[lane + 32 * k];
        wp[k] = W_pi  [lane + 32 * k];
    }

    const int       gwarp = (blockIdx.x * blockDim.x + tid) >> 5;
    const long long wbase = (long long)gwarp * (4 * ITERS);

#pragma unroll 1
    for (int it = 0; it < ITERS; ++it) {
        const long long base = wbase + (long long)it * 4;
        if (base >= E) break;

        // Lanes 0..3 (replicated 8x) load the 4 edges' indices; 1 wf each.
        const int       jl   = lane & 3;
        const long long e_l  = base + jl;
        const int       e_lc = (e_l < E) ? (int)e_l : (E - 1);
        const int s_l = src_idx[e_lc];
        const int g_l = dst_idx[e_lc];

        float val[12];

        // Whole warp processes edge j: rows via converged LDG.32 (1 line/instr).
#pragma unroll
        for (int j = 0; j < 4; ++j) {
            const int s_j = __shfl_sync(0xFFFFFFFFu, s_l, j);
            const int g_j = __shfl_sync(0xFFFFFFFFu, g_l, j);

            const float* __restrict__ up = ufeats + (size_t)s_j * 128 + lane;
            const float* __restrict__ vp = ifeats + (size_t)g_j * 128 + lane;

            const float u0 = up[0],  u1 = up[32], u2 = up[64], u3 = up[96];
            const float v0 = vp[0],  v1 = vp[32], v2 = vp[64], v3 = vp[96];

            const float h0 = u0 * v0;
            const float h1 = u1 * v1;
            const float h2 = u2 * v2;
            const float h3 = u3 * v3;

            val[3*j+0] = fmaf(h0, wm[0], fmaf(h1, wm[1], fmaf(h2, wm[2], h3 * wm[3])));
            val[3*j+1] = fmaf(h0, wd[0], fmaf(h1, wd[1], fmaf(h2, wd[2], h3 * wd[3])));
            val[3*j+2] = fmaf(h0, wp[0], fmaf(h1, wp[1], fmaf(h2, wp[2], h3 * wp[3])));
        }

        // ---- Reduce-scatter: 12 -> 6 (xor 16). Low half keeps edges 0,1;
        //      high half keeps edges 2,3 (renumbered to val[0..5]).
#pragma unroll
        for (int i = 0; i < 6; ++i) {
            const bool  hi   = (lane & 16) != 0;
            const float send = hi ? val[i]     : val[i + 6];
            const float keep = hi ? val[i + 6] : val[i];
            val[i] = keep + __shfl_xor_sync(0xFFFFFFFFu, send, 16);
        }
        // ---- 6 -> 3 (xor 8). Octet o now owns edge o's (sm, sd, sp).
#pragma unroll
        for (int i = 0; i < 3; ++i) {
            const bool  hi   = (lane & 8) != 0;
            const float send = hi ? val[i]     : val[i + 3];
            const float keep = hi ? val[i + 3] : val[i];
            val[i] = keep + __shfl_xor_sync(0xFFFFFFFFu, send, 8);
        }
        // ---- Butterfly within each octet (xor 4, 2, 1).
#pragma unroll
        for (int off = 4; off >= 1; off >>= 1) {
            val[0] += __shfl_xor_sync(0xFFFFFFFFu, val[0], off);
            val[1] += __shfl_xor_sync(0xFFFFFFFFu, val[1], off);
            val[2] += __shfl_xor_sync(0xFFFFFFFFu, val[2], off);
        }

        // Leaders (lanes 0,8,16,24) handle edge (lane>>3). Fetch that edge's
        // s,g from the index-holder lane (lane j holds edge j's indices).
        const int o   = lane >> 3;
        const int s_o = __shfl_sync(0xFFFFFFFFu, s_l, o);
        const int g_o = __shfl_sync(0xFFFFFFFFu, g_l, o);

        if ((lane & 7) == 0) {
            const long long e_ll = base + o;
            if (e_ll < E) {
                const int e = (int)e_ll;

                const float gef = ge_factor[g_o];
                const float szf = sz_factor[s_o];

                const float mu_sig = fast_sigmoid(val[0] + bm);
                const float pi_v   = fast_sigmoid(val[2] + bp);

                // stable softplus: max(x,0) + log(1 + exp(-|x|))
                const float x = gef * (val[1] + bd);
                float disp = fmaxf(x, 0.0f) + __logf(1.0f + __expf(-fabsf(x)));
                disp = fminf(fmaxf(disp, 1e-4f), 1e4f);

                float mu = __expf(gef * mu_sig) - 1.0f;   // arg in [0,1]
                mu = fminf(fmaxf(mu, 1e-5f), 1e6f);
                mu *= szf;

                out[e]                       = mu;
                out[(size_t)E + e]           = disp;
                out[(size_t)2 * E + e]       = pi_v;
            }
        }
    }
}

extern "C" void kernel_launch(void* const* d_in, const int* in_sizes, int n_in,
                              void* d_out, int out_size)
{
    const float* ufeats    = (const float*)d_in[0];
    const float* ifeats    = (const float*)d_in[1];
    const float* ge_factor = (const float*)d_in[2];
    const float* sz_factor = (const float*)d_in[3];
    const float* W_mean    = (const float*)d_in[4];
    const float* b_mean    = (const float*)d_in[5];
    const float* W_disp    = (const float*)d_in[6];
    const float* b_disp    = (const float*)d_in[7];
    const float* W_pi      = (const float*)d_in[8];
    const float* b_pi      = (const float*)d_in[9];
    const int*   src_idx   = (const int*)d_in[10];
    const int*   dst_idx   = (const int*)d_in[11];
    float* out = (float*)d_out;
    (void)n_in; (void)out_size;

    const int E = in_sizes[10];

    // 32 edges per warp, 8 warps per block -> 256 edges per block.
    const int threads = 256;
    const long long edges_per_block = 8LL * 4 * ITERS;
    const int blocks = (int)(((long long)E + edges_per_block - 1) / edges_per_block);

    zinb_kernel<<<blocks, threads>>>(
        ufeats, ifeats, ge_factor, sz_factor,
        W_mean, b_mean, W_disp, b_disp, W_pi, b_pi,
        src_idx, dst_idx, out, E);
}

// round 6
// speedup vs baseline: 1.4990x; 1.1728x over previous
#include <cuda_runtime.h>
#include <math.h>

// ZINBDecoder, converged-load layout, 8-edge reduce-scatter:
//   - whole warp cooperates on one edge's rows (LDG.32, 1 line/instr)
//   - 8 edges per iteration, ITERS iterations per warp
//   - weights register-resident: 12 scalar regs (W[lane+32k])
//   - fold 24 partials (8 edges x 3 sums) via xor16/8/4, butterfly xor2/1;
//     quad q (lanes 4q..4q+3) ends up owning edge q's (sm, sd, sp).
// out = [mu | disp | pi], fp32.

#define ITERS 4   // 8 edges/iter -> 32 edges per warp

__device__ __forceinline__ float fast_sigmoid(float x) {
    return __fdividef(1.0f, 1.0f + __expf(-x));
}

__global__ void __launch_bounds__(256)
zinb_kernel(const float* __restrict__ ufeats,
            const float* __restrict__ ifeats,
            const float* __restrict__ ge_factor,
            const float* __restrict__ sz_factor,
            const float* __restrict__ W_mean,
            const float* __restrict__ b_mean,
            const float* __restrict__ W_disp,
            const float* __restrict__ b_disp,
            const float* __restrict__ W_pi,
            const float* __restrict__ b_pi,
            const int*   __restrict__ src_idx,
            const int*   __restrict__ dst_idx,
            float* __restrict__ out,
            int E)
{
    const int tid  = threadIdx.x;
    const int lane = tid & 31;

    const float bm = b_mean[0];
    const float bd = b_disp[0];
    const float bp = b_pi[0];

    // Weight slices in registers: element (lane + 32k), k = 0..3.
    float wm[4], wd[4], wp[4];
#pragma unroll
    for (int k = 0; k < 4; ++k) {
        wm[k] = W_mean[lane + 32 * k];
        wd[k] = W_disp[lane + 32 * k];
        wp[k] = W_pi  [lane + 32 * k];
    }

    const int       gwarp = (blockIdx.x * blockDim.x + tid) >> 5;
    const long long wbase = (long long)gwarp * (8 * ITERS);

#pragma unroll 1
    for (int it = 0; it < ITERS; ++it) {
        const long long base = wbase + (long long)it * 8;
        if (base >= E) break;

        // Lanes 0..7 (replicated 4x) hold the 8 edges' indices; 1 wf each.
        const int       jl   = lane & 7;
        const long long e_l  = base + jl;
        const int       e_lc = (e_l < E) ? (int)e_l : (E - 1);
        const int s_l = src_idx[e_lc];
        const int g_l = dst_idx[e_lc];

        float val[24];

        // Whole warp processes edge j: rows via converged LDG.32 (1 line/instr).
#pragma unroll
        for (int j = 0; j < 8; ++j) {
            const int s_j = __shfl_sync(0xFFFFFFFFu, s_l, j);
            const int g_j = __shfl_sync(0xFFFFFFFFu, g_l, j);

            const float* __restrict__ up = ufeats + (size_t)s_j * 128 + lane;
            const float* __restrict__ vp = ifeats + (size_t)g_j * 128 + lane;

            const float u0 = up[0],  u1 = up[32], u2 = up[64], u3 = up[96];
            const float v0 = vp[0],  v1 = vp[32], v2 = vp[64], v3 = vp[96];

            const float h0 = u0 * v0;
            const float h1 = u1 * v1;
            const float h2 = u2 * v2;
            const float h3 = u3 * v3;

            val[3*j+0] = fmaf(h0, wm[0], fmaf(h1, wm[1], fmaf(h2, wm[2], h3 * wm[3])));
            val[3*j+1] = fmaf(h0, wd[0], fmaf(h1, wd[1], fmaf(h2, wd[2], h3 * wd[3])));
            val[3*j+2] = fmaf(h0, wp[0], fmaf(h1, wp[1], fmaf(h2, wp[2], h3 * wp[3])));
        }

        // ---- Fold 24 -> 12 (xor 16): edge bit2 := lane bit4.
#pragma unroll
        for (int i = 0; i < 12; ++i) {
            const bool  hi   = (lane & 16) != 0;
            const float send = hi ? val[i]      : val[i + 12];
            const float keep = hi ? val[i + 12] : val[i];
            val[i] = keep + __shfl_xor_sync(0xFFFFFFFFu, send, 16);
        }
        // ---- 12 -> 6 (xor 8): edge bit1 := lane bit3.
#pragma unroll
        for (int i = 0; i < 6; ++i) {
            const bool  hi   = (lane & 8) != 0;
            const float send = hi ? val[i]     : val[i + 6];
            const float keep = hi ? val[i + 6] : val[i];
            val[i] = keep + __shfl_xor_sync(0xFFFFFFFFu, send, 8);
        }
        // ---- 6 -> 3 (xor 4): edge bit0 := lane bit2. Quad q owns edge q.
#pragma unroll
        for (int i = 0; i < 3; ++i) {
            const bool  hi   = (lane & 4) != 0;
            const float send = hi ? val[i]     : val[i + 3];
            const float keep = hi ? val[i + 3] : val[i];
            val[i] = keep + __shfl_xor_sync(0xFFFFFFFFu, send, 4);
        }
        // ---- Butterfly within each quad (xor 2, 1).
#pragma unroll
        for (int off = 2; off >= 1; off >>= 1) {
            val[0] += __shfl_xor_sync(0xFFFFFFFFu, val[0], off);
            val[1] += __shfl_xor_sync(0xFFFFFFFFu, val[1], off);
            val[2] += __shfl_xor_sync(0xFFFFFFFFu, val[2], off);
        }

        // Leaders (lanes 0,4,...,28) handle edge (lane>>2); fetch that edge's
        // s,g from index-holder lane (lane j holds edge j's indices).
        const int o   = lane >> 2;
        const int s_o = __shfl_sync(0xFFFFFFFFu, s_l, o);
        const int g_o = __shfl_sync(0xFFFFFFFFu, g_l, o);

        if ((lane & 3) == 0) {
            const long long e_ll = base + o;
            if (e_ll < E) {
                const int e = (int)e_ll;

                const float gef = ge_factor[g_o];
                const float szf = sz_factor[s_o];

                const float mu_sig = fast_sigmoid(val[0] + bm);
                const float pi_v   = fast_sigmoid(val[2] + bp);

                // stable softplus: max(x,0) + log(1 + exp(-|x|))
                const float x = gef * (val[1] + bd);
                float disp = fmaxf(x, 0.0f) + __logf(1.0f + __expf(-fabsf(x)));
                disp = fminf(fmaxf(disp, 1e-4f), 1e4f);

                float mu = __expf(gef * mu_sig) - 1.0f;   // arg in [0,1]
                mu = fminf(fmaxf(mu, 1e-5f), 1e6f);
                mu *= szf;

                out[e]                 = mu;
                out[(size_t)E + e]     = disp;
                out[(size_t)2 * E + e] = pi_v;
            }
        }
    }
}

extern "C" void kernel_launch(void* const* d_in, const int* in_sizes, int n_in,
                              void* d_out, int out_size)
{
    const float* ufeats    = (const float*)d_in[0];
    const float* ifeats    = (const float*)d_in[1];
    const float* ge_factor = (const float*)d_in[2];
    const float* sz_factor = (const float*)d_in[3];
    const float* W_mean    = (const float*)d_in[4];
    const float* b_mean    = (const float*)d_in[5];
    const float* W_disp    = (const float*)d_in[6];
    const float* b_disp    = (const float*)d_in[7];
    const float* W_pi      = (const float*)d_in[8];
    const float* b_pi      = (const float*)d_in[9];
    const int*   src_idx   = (const int*)d_in[10];
    const int*   dst_idx   = (const int*)d_in[11];
    float* out = (float*)d_out;
    (void)n_in; (void)out_size;

    const int E = in_sizes[10];

    // 32 edges per warp, 8 warps per block -> 256 edges per block.
    const int threads = 256;
    const long long edges_per_block = 8LL * 8 * ITERS;
    const int blocks = (int)(((long long)E + edges_per_block - 1) / edges_per_block);

    zinb_kernel<<<blocks, threads>>>(
        ufeats, ifeats, ge_factor, sz_factor,
        W_mean, b_mean, W_disp, b_disp, W_pi, b_pi,
        src_idx, dst_idx, out, E);
}